// round 1
// baseline (speedup 1.0000x reference)
#include <cuda_runtime.h>

#define N_NODES 10000
#define N_EDGES 320000
#define D_IN    128
#define D_HID   64
#define D_OUT   16
#define NH      (N_NODES * D_HID)   // 640000
#define AAM     5

// ---------------- device scratch (no allocation allowed) ----------------
__device__ float  g_b[NH];
__device__ float  g_X[AAM][NH];
__device__ float  g_F[AAM][NH];
__device__ float  g_w[NH];          // SPMM input  w = 2relu(u)-u+b
__device__ float  g_u[NH];          // last AA combine result
__device__ float  g_ThT[D_HID * D_HID];   // ThT[k*64+c] = Theta[c][k]
__device__ int    g_rowptr[N_NODES + 1];
__device__ int    g_cur[N_NODES];   // counts, then scatter cursors
__device__ int    g_srcs[N_EDGES];  // CSR (sorted by dst)
__device__ float  g_ews[N_EDGES];
__device__ double g_GG[15];         // upper-tri Gram of G = F - X
__device__ float  g_a[AAM];

// ---------------- CSR build ----------------
__global__ void k_zero_cnt() {
    int i = blockIdx.x * blockDim.x + threadIdx.x;
    if (i < N_NODES) g_cur[i] = 0;
}

__global__ void k_hist(const int* __restrict__ dst) {
    int e = blockIdx.x * blockDim.x + threadIdx.x;
    if (e < N_EDGES) atomicAdd(&g_cur[dst[e]], 1);
}

__global__ void k_scan() {  // one block, 1024 threads
    __shared__ int part[1024];
    const int CH = (N_NODES + 1023) / 1024;  // 10
    int t = threadIdx.x;
    int beg = t * CH;
    int end = beg + CH; if (end > N_NODES) end = N_NODES;
    int s = 0;
    for (int i = beg; i < end; i++) s += g_cur[i];
    part[t] = s;
    __syncthreads();
    for (int d = 1; d < 1024; d <<= 1) {
        int v = (t >= d) ? part[t - d] : 0;
        __syncthreads();
        part[t] += v;
        __syncthreads();
    }
    int off = (t > 0) ? part[t - 1] : 0;
    for (int i = beg; i < end; i++) {
        int c = g_cur[i];
        g_rowptr[i] = off;
        g_cur[i]    = off;   // scatter cursor
        off += c;
    }
    if (t == 0) g_rowptr[N_NODES] = N_EDGES;
}

__global__ void k_scatter(const int* __restrict__ src, const int* __restrict__ dst,
                          const float* __restrict__ ew) {
    int e = blockIdx.x * blockDim.x + threadIdx.x;
    if (e >= N_EDGES) return;
    int d = dst[e];
    int p = atomicAdd(&g_cur[d], 1);
    g_srcs[p] = src[e];
    g_ews[p]  = ew[e];
}

// ---------------- Cayley: Theta = (I+Om)^-1 (I-Om), Gauss-Jordan ----------------
__global__ void k_theta(const float* __restrict__ B) {  // one block, 256 threads
    __shared__ float M[64][128];
    __shared__ float fct[64];
    int tid = threadIdx.x;
    for (int idx = tid; idx < 64 * 64; idx += 256) {
        int i = idx >> 6, j = idx & 63;
        float om = 0.5f * (B[i * 64 + j] - B[j * 64 + i]);
        float e  = (i == j) ? 1.f : 0.f;
        M[i][j]      = e + om;   // I + Om
        M[i][64 + j] = e - om;   // I - Om
    }
    __syncthreads();
    for (int k = 0; k < 64; k++) {
        float inv = 1.f / M[k][k];   // I+Om has symmetric part I -> no pivoting needed
        __syncthreads();
        for (int j = tid; j < 128; j += 256) M[k][j] *= inv;
        __syncthreads();
        for (int r = tid; r < 64; r += 256) fct[r] = M[r][k];
        __syncthreads();
        for (int idx = tid; idx < 64 * 128; idx += 256) {
            int r = idx >> 7, j = idx & 127;
            if (r != k) M[r][j] -= fct[r] * M[k][j];
        }
        __syncthreads();
    }
    for (int idx = tid; idx < 64 * 64; idx += 256) {
        int k = idx >> 6, c = idx & 63;
        g_ThT[idx] = M[c][64 + k];   // ThT[k][c] = Theta[c][k]
    }
}

// ---------------- encoder: b[n,c] = x[n,:] @ enc_W[:,c] + enc_b[c] ----------------
__global__ void k_encode(const float* __restrict__ x, const float* __restrict__ W,
                         const float* __restrict__ bias) {
    __shared__ float Ws[D_IN * D_HID];   // 32 KB
    __shared__ float xs[4][D_IN];
    int tid = threadIdx.x;
    for (int i = tid; i < D_IN * D_HID; i += 256) Ws[i] = W[i];
    int node0 = blockIdx.x * 4;
    for (int i = tid; i < 4 * D_IN; i += 256)
        xs[i / D_IN][i % D_IN] = x[(node0 + i / D_IN) * D_IN + (i % D_IN)];
    __syncthreads();
    int ln = tid >> 6;       // node within block
    int c  = tid & 63;       // channel
    float acc = bias[c];
#pragma unroll 8
    for (int k = 0; k < D_IN; k++) acc = fmaf(xs[ln][k], Ws[k * 64 + c], acc);
    g_b[(node0 + ln) * 64 + c] = acc;
}

// ---------------- w = 2relu(u)-u+b, and copy u -> X[slot] ----------------
__global__ void k_prep(int uslot, int xslot) {
    int t = blockIdx.x * blockDim.x + threadIdx.x;
    if (t >= NH) return;
    float u = (uslot < 0) ? g_b[t] : g_F[uslot][t];
    g_X[xslot][t] = u;
    g_w[t] = 2.f * fmaxf(u, 0.f) - u + g_b[t];
}

// ---------------- fused SPMM + channel mix:  F[slot] = b + 0.5 * Theta @ spmm(w) ----------------
__global__ void k_spmm(int f_slot) {
    __shared__ float sTh[D_HID * D_HID];   // 16 KB, ThT layout
    for (int i = threadIdx.x; i < D_HID * D_HID; i += blockDim.x) sTh[i] = g_ThT[i];
    __syncthreads();
    int warp = threadIdx.x >> 5;
    int lane = threadIdx.x & 31;
    int node = blockIdx.x * (blockDim.x >> 5) + warp;
    if (node >= N_NODES) return;
    int beg = g_rowptr[node], end = g_rowptr[node + 1];
    const float* __restrict__ wv = g_w;
    float a0 = 0.f, a1 = 0.f;   // s[lane], s[lane+32]
    for (int e = beg; e < end; ++e) {
        int   s  = g_srcs[e];
        float ww = g_ews[e];
        a0 = fmaf(ww, wv[s * 64 + lane], a0);
        a1 = fmaf(ww, wv[s * 64 + 32 + lane], a1);
    }
    float o0 = 0.f, o1 = 0.f;   // out channels lane, lane+32
#pragma unroll
    for (int k = 0; k < 32; ++k) {
        float sk  = __shfl_sync(0xffffffffu, a0, k);   // s[k]
        float sk2 = __shfl_sync(0xffffffffu, a1, k);   // s[k+32]
        o0 = fmaf(sTh[k * 64 + lane],             sk,  o0);
        o1 = fmaf(sTh[k * 64 + 32 + lane],        sk,  o1);
        o0 = fmaf(sTh[(k + 32) * 64 + lane],      sk2, o0);
        o1 = fmaf(sTh[(k + 32) * 64 + 32 + lane], sk2, o1);
    }
    float* out = g_F[f_slot];
    out[node * 64 + lane]      = g_b[node * 64 + lane]      + 0.5f * o0;
    out[node * 64 + 32 + lane] = g_b[node * 64 + 32 + lane] + 0.5f * o1;
}

// ---------------- Anderson: Gram of G = F - X (15 upper-tri entries) ----------------
__global__ void k_zero_gg() {
    if (threadIdx.x < 15) g_GG[threadIdx.x] = 0.0;
}

__global__ void k_dots() {
    float p[15];
#pragma unroll
    for (int i = 0; i < 15; i++) p[i] = 0.f;
    int stride = gridDim.x * blockDim.x;
    for (int t = blockIdx.x * blockDim.x + threadIdx.x; t < NH; t += stride) {
        float g[5];
#pragma unroll
        for (int i = 0; i < 5; i++) g[i] = g_F[i][t] - g_X[i][t];
        int c = 0;
#pragma unroll
        for (int i = 0; i < 5; i++)
#pragma unroll
            for (int j = i; j < 5; j++) { p[c] = fmaf(g[i], g[j], p[c]); c++; }
    }
#pragma unroll
    for (int i = 0; i < 15; i++) {
        float v = p[i];
        for (int o = 16; o > 0; o >>= 1) v += __shfl_down_sync(0xffffffffu, v, o);
        if ((threadIdx.x & 31) == 0) atomicAdd(&g_GG[i], (double)v);
    }
}

__global__ void k_solve5() {   // 1 thread: solve (GG + lam I) a = 1, normalize
    if (threadIdx.x != 0 || blockIdx.x != 0) return;
    double M[5][6];
    double gg[15];
    for (int i = 0; i < 15; i++) gg[i] = g_GG[i];
    int c = 0;
    for (int i = 0; i < 5; i++)
        for (int j = i; j < 5; j++) { M[i][j] = gg[c]; M[j][i] = gg[c]; c++; }
    for (int i = 0; i < 5; i++) { M[i][i] += 1e-4; M[i][5] = 1.0; }
    for (int k = 0; k < 5; k++) {
        int piv = k; double mx = fabs(M[k][k]);
        for (int r = k + 1; r < 5; r++)
            if (fabs(M[r][k]) > mx) { mx = fabs(M[r][k]); piv = r; }
        if (piv != k)
            for (int j = 0; j < 6; j++) { double t = M[k][j]; M[k][j] = M[piv][j]; M[piv][j] = t; }
        double inv = 1.0 / M[k][k];
        for (int r = k + 1; r < 5; r++) {
            double f = M[r][k] * inv;
            for (int j = k; j < 6; j++) M[r][j] -= f * M[k][j];
        }
    }
    double a[5];
    for (int k = 4; k >= 0; k--) {
        double s = M[k][5];
        for (int j = k + 1; j < 5; j++) s -= M[k][j] * a[j];
        a[k] = s / M[k][k];
    }
    double sum = a[0] + a[1] + a[2] + a[3] + a[4];
    for (int i = 0; i < 5; i++) g_a[i] = (float)(a[i] / sum);
}

// ---------------- u_new = a @ F ; X[slot]=u_new ; w=2relu(u_new)-u_new+b ----------------
__global__ void k_combine(int xslot) {
    int t = blockIdx.x * blockDim.x + threadIdx.x;
    if (t >= NH) return;
    float a0 = g_a[0], a1 = g_a[1], a2 = g_a[2], a3 = g_a[3], a4 = g_a[4];
    float un = a0 * g_F[0][t] + a1 * g_F[1][t] + a2 * g_F[2][t]
             + a3 * g_F[3][t] + a4 * g_F[4][t];
    g_u[t] = un;
    g_X[xslot][t] = un;
    g_w[t] = 2.f * fmaxf(un, 0.f) - un + g_b[t];
}

// ---------------- decoder: out[n,o] = relu(u[n,:]) @ dec_W[:,o] ----------------
__global__ void k_decode(const float* __restrict__ decW, float* __restrict__ out) {
    __shared__ float Ws[D_HID * D_OUT];   // 4 KB
    for (int i = threadIdx.x; i < D_HID * D_OUT; i += 256) Ws[i] = decW[i];
    __syncthreads();
    int ln = threadIdx.x >> 4;            // 16 nodes / block
    int o  = threadIdx.x & 15;
    int n  = blockIdx.x * 16 + ln;
    if (n >= N_NODES) return;
    float acc = 0.f;
#pragma unroll
    for (int d = 0; d < D_HID; d++)
        acc = fmaf(fmaxf(g_u[n * 64 + d], 0.f), Ws[d * 16 + o], acc);
    out[n * 16 + o] = acc;
}

// ---------------- launch ----------------
extern "C" void kernel_launch(void* const* d_in, const int* in_sizes, int n_in,
                              void* d_out, int out_size) {
    const float* x    = (const float*)d_in[0];
    const int*   ei   = (const int*)  d_in[1];
    const float* ew   = (const float*)d_in[2];
    const float* encW = (const float*)d_in[3];
    const float* encb = (const float*)d_in[4];
    const float* cayB = (const float*)d_in[5];
    const float* decW = (const float*)d_in[6];
    float* out = (float*)d_out;

    const int* src = ei;              // edge_index[0]
    const int* dst = ei + N_EDGES;    // edge_index[1]

    // one-time per launch: CSR + Theta + encoder
    k_zero_cnt<<<(N_NODES + 255) / 256, 256>>>();
    k_hist<<<(N_EDGES + 255) / 256, 256>>>(dst);
    k_scan<<<1, 1024>>>();
    k_scatter<<<(N_EDGES + 255) / 256, 256>>>(src, dst, ew);
    k_theta<<<1, 256>>>(cayB);
    k_encode<<<N_NODES / 4, 256>>>(x, encW, encb);

    // 5 plain PR sweeps filling Anderson history: X[i]=u_i, F[i]=g(u_i)
    for (int i = 0; i < AAM; i++) {
        k_prep<<<NH / 256, 256>>>(i - 1, i);   // uslot=-1 -> u0 = b
        k_spmm<<<N_NODES / 8, 256>>>(i);
    }

    // 5 Anderson-accelerated sweeps (last g() is dead -> skip its SPMM)
    for (int k = 0; k < AAM; k++) {
        k_zero_gg<<<1, 32>>>();
        k_dots<<<296, 256>>>();
        k_solve5<<<1, 1>>>();
        k_combine<<<NH / 256, 256>>>(k);
        if (k < AAM - 1) k_spmm<<<N_NODES / 8, 256>>>(k);
    }

    k_decode<<<N_NODES / 16, 256>>>(decW, out);
}

// round 2
// speedup vs baseline: 1.5113x; 1.5113x over previous
#include <cuda_runtime.h>

#define N_NODES 10000
#define N_EDGES 320000
#define D_IN    128
#define D_HID   64
#define D_OUT   16
#define NH      (N_NODES * D_HID)   // 640000
#define AAM     5

// ---------------- device scratch (no allocation allowed) ----------------
__device__ float  g_b[NH];
__device__ float  g_u[NH];                 // current u
__device__ float  g_w[NH];                 // SPMM input  w = 2relu(u)-u+b
__device__ float  g_F[AAM][NH];
__device__ float  g_G[AAM][NH];            // G = F - X
__device__ float  g_ThT[D_HID * D_HID];    // ThT[k*64+c] = Theta[c][k]
__device__ int    g_rowptr[N_NODES + 1];
__device__ int    g_cur[N_NODES];
__device__ int2   g_edge[N_EDGES];         // {src, float_as_int(ew)} CSR-sorted by dst
__device__ double g_GGbuf[2][15];          // ping-pong persistent Gram (lower-tri packed)
__device__ double g_GGrow[2][5];           // per-iteration updated Gram row

// ---------------- CSR build ----------------
__global__ void k_zero_cnt() {
    int i = blockIdx.x * blockDim.x + threadIdx.x;
    if (i < N_NODES) g_cur[i] = 0;
}

__global__ void k_hist(const int* __restrict__ dst) {
    int e = blockIdx.x * blockDim.x + threadIdx.x;
    if (e < N_EDGES) atomicAdd(&g_cur[dst[e]], 1);
}

__global__ void k_scan() {  // one block, 1024 threads
    __shared__ int part[1024];
    const int CH = (N_NODES + 1023) / 1024;
    int t = threadIdx.x;
    int beg = t * CH;
    int end = beg + CH; if (end > N_NODES) end = N_NODES;
    int s = 0;
    for (int i = beg; i < end; i++) s += g_cur[i];
    part[t] = s;
    __syncthreads();
    for (int d = 1; d < 1024; d <<= 1) {
        int v = (t >= d) ? part[t - d] : 0;
        __syncthreads();
        part[t] += v;
        __syncthreads();
    }
    int off = (t > 0) ? part[t - 1] : 0;
    for (int i = beg; i < end; i++) {
        int c = g_cur[i];
        g_rowptr[i] = off;
        g_cur[i]    = off;
        off += c;
    }
    if (t == 0) g_rowptr[N_NODES] = N_EDGES;
}

__global__ void k_scatter(const int* __restrict__ src, const int* __restrict__ dst,
                          const float* __restrict__ ew) {
    int e = blockIdx.x * blockDim.x + threadIdx.x;
    if (e >= N_EDGES) return;
    int d = dst[e];
    int p = atomicAdd(&g_cur[d], 1);
    g_edge[p] = make_int2(src[e], __float_as_int(ew[e]));
}

// ---------------- Cayley: Theta = (I+Om)^-1 (I-Om), Gauss-Jordan ----------------
__global__ void k_theta(const float* __restrict__ B) {  // one block, 256 threads
    __shared__ float M[64][128];
    __shared__ float fct[64];
    int tid = threadIdx.x;
    for (int idx = tid; idx < 64 * 64; idx += 256) {
        int i = idx >> 6, j = idx & 63;
        float om = 0.5f * (B[i * 64 + j] - B[j * 64 + i]);
        float e  = (i == j) ? 1.f : 0.f;
        M[i][j]      = e + om;   // I + Om
        M[i][64 + j] = e - om;   // I - Om
    }
    __syncthreads();
    for (int k = 0; k < 64; k++) {
        float inv = 1.f / M[k][k];
        __syncthreads();
        for (int j = tid; j < 128; j += 256) M[k][j] *= inv;
        __syncthreads();
        for (int r = tid; r < 64; r += 256) fct[r] = M[r][k];
        __syncthreads();
        for (int idx = tid; idx < 64 * 128; idx += 256) {
            int r = idx >> 7, j = idx & 127;
            if (r != k) M[r][j] -= fct[r] * M[k][j];
        }
        __syncthreads();
    }
    for (int idx = tid; idx < 64 * 64; idx += 256) {
        int k = idx >> 6, c = idx & 63;
        g_ThT[idx] = M[c][64 + k];   // ThT[k][c] = Theta[c][k]
    }
}

// ---------------- encoder: b[n,c] = x[n,:] @ enc_W[:,c] + enc_b[c] ----------------
// 8 nodes/block, thread = (node ln, channel-pair c'), float2 weights
__global__ void k_encode(const float* __restrict__ x, const float* __restrict__ W,
                         const float* __restrict__ bias) {
    __shared__ float2 Ws2[D_IN][32];   // 32 KB
    __shared__ float  xs[8][D_IN];     // 4 KB
    int tid = threadIdx.x;
    for (int i = tid; i < D_IN * 32; i += 256)
        ((float2*)Ws2)[i] = ((const float2*)W)[i];
    int node0 = blockIdx.x * 8;
    for (int i = tid; i < 8 * D_IN; i += 256)
        xs[i >> 7][i & 127] = x[node0 * D_IN + i];
    __syncthreads();
    int ln = tid >> 5;       // node within block (warp = one node)
    int cp = tid & 31;       // channel pair
    float2 acc = ((const float2*)bias)[cp];
#pragma unroll 8
    for (int k = 0; k < D_IN; k++) {
        float  xk = xs[ln][k];
        float2 w2 = Ws2[k][cp];
        acc.x = fmaf(xk, w2.x, acc.x);
        acc.y = fmaf(xk, w2.y, acc.y);
    }
    ((float2*)g_b)[(node0 + ln) * 32 + cp] = acc;
}

// ---------------- prep0: u = b, w = 2relu(b); zero GGbuf[0] ----------------
__global__ void k_prep0() {
    if (blockIdx.x == 0 && threadIdx.x < 15) g_GGbuf[0][threadIdx.x] = 0.0;
    int t = blockIdx.x * blockDim.x + threadIdx.x;
    if (t >= NH) return;
    float bb = g_b[t];
    g_u[t] = bb;
    g_w[t] = 2.f * fmaxf(bb, 0.f);
}

// ---------------- fused SPMM + mix + G + Gram partials (+ next-u/w) ----------------
// F[slot] = b + 0.5 * Theta @ spmm(w);  G[slot] = F[slot] - u
// accumulates dot(G[slot], G[j]) for j in [0, npairs) into target
// hist=1 -> target = &g_GGbuf[0][base_off] ; hist=0 -> target = g_GGrow[base_off]
__global__ void k_spmm(int slot, int npairs, int hist, int base_off, int write_next) {
    __shared__ float2 sTh[D_HID][32];     // sTh[k][c'] = (Theta[2c'][k], Theta[2c'+1][k])
    __shared__ double red[8][5];
    for (int i = threadIdx.x; i < D_HID * 32; i += blockDim.x)
        ((float2*)sTh)[i] = ((const float2*)g_ThT)[i];
    __syncthreads();

    int warp = threadIdx.x >> 5;
    int lane = threadIdx.x & 31;
    int node = blockIdx.x * 8 + warp;     // grid = 1250 * 8 = exactly N_NODES
    int beg = g_rowptr[node], end = g_rowptr[node + 1];

    const int2*   __restrict__ eg = g_edge;
    const float2* __restrict__ wv = (const float2*)g_w;

    float2 acc = make_float2(0.f, 0.f);
    int e = beg;
    for (; e + 4 <= end; e += 4) {
        int2 e0 = eg[e], e1 = eg[e + 1], e2 = eg[e + 2], e3 = eg[e + 3];
        float2 v0 = wv[e0.x * 32 + lane];
        float2 v1 = wv[e1.x * 32 + lane];
        float2 v2 = wv[e2.x * 32 + lane];
        float2 v3 = wv[e3.x * 32 + lane];
        float w0 = __int_as_float(e0.y), w1 = __int_as_float(e1.y);
        float w2 = __int_as_float(e2.y), w3 = __int_as_float(e3.y);
        acc.x = fmaf(w0, v0.x, acc.x); acc.y = fmaf(w0, v0.y, acc.y);
        acc.x = fmaf(w1, v1.x, acc.x); acc.y = fmaf(w1, v1.y, acc.y);
        acc.x = fmaf(w2, v2.x, acc.x); acc.y = fmaf(w2, v2.y, acc.y);
        acc.x = fmaf(w3, v3.x, acc.x); acc.y = fmaf(w3, v3.y, acc.y);
    }
    for (; e < end; ++e) {
        int2 ed = eg[e];
        float2 v = wv[ed.x * 32 + lane];
        float ww = __int_as_float(ed.y);
        acc.x = fmaf(ww, v.x, acc.x);
        acc.y = fmaf(ww, v.y, acc.y);
    }

    // channel mix: o[2l], o[2l+1] = Theta @ s ; s[2m]=acc.x@lane m, s[2m+1]=acc.y@lane m
    float2 o = make_float2(0.f, 0.f);
#pragma unroll
    for (int m = 0; m < 32; ++m) {
        float sx = __shfl_sync(0xffffffffu, acc.x, m);
        float sy = __shfl_sync(0xffffffffu, acc.y, m);
        float2 t0 = sTh[2 * m][lane];
        float2 t1 = sTh[2 * m + 1][lane];
        o.x = fmaf(t0.x, sx, o.x); o.y = fmaf(t0.y, sx, o.y);
        o.x = fmaf(t1.x, sy, o.x); o.y = fmaf(t1.y, sy, o.y);
    }

    int row = node * 32 + lane;
    float2 bb = ((const float2*)g_b)[row];
    float2 val = make_float2(bb.x + 0.5f * o.x, bb.y + 0.5f * o.y);
    ((float2*)g_F[slot])[row] = val;

    float2 uu = ((const float2*)g_u)[row];
    float2 gn = make_float2(val.x - uu.x, val.y - uu.y);
    ((float2*)g_G[slot])[row] = gn;

    if (write_next) {   // history phase: u_{i+1} = F[i], w = 2relu(u)-u+b
        ((float2*)g_u)[row] = val;
        float2 wn = make_float2(2.f * fmaxf(val.x, 0.f) - val.x + bb.x,
                                2.f * fmaxf(val.y, 0.f) - val.y + bb.y);
        ((float2*)g_w)[row] = wn;
    }

    // Gram partials: p_j = dot(gn, G_j)
    float p[5];
#pragma unroll
    for (int j = 0; j < 5; ++j) p[j] = 0.f;
    for (int j = 0; j < npairs; ++j) {
        float2 gj = (j == slot) ? gn : ((const float2*)g_G[j])[row];
        p[j] = gn.x * gj.x + gn.y * gj.y;
    }
#pragma unroll
    for (int j = 0; j < 5; ++j)
        for (int off = 16; off > 0; off >>= 1)
            p[j] += __shfl_down_sync(0xffffffffu, p[j], off);
    if (lane == 0)
        for (int j = 0; j < 5; ++j) red[warp][j] = (double)p[j];
    __syncthreads();
    if (threadIdx.x < npairs) {
        int j = threadIdx.x;
        double s = red[0][j] + red[1][j] + red[2][j] + red[3][j]
                 + red[4][j] + red[5][j] + red[6][j] + red[7][j];
        double* target = hist ? &g_GGbuf[0][base_off] : g_GGrow[base_off];
        atomicAdd(&target[j], s);
    }
}

// ---------------- combine(k): merge Gram row, solve 5x5, u_new = a@F, prep w ----------------
__global__ void k_combine(int k) {
    __shared__ float sa[5];
    if (threadIdx.x == 0) {
        double M[5][5];
        const double* base = g_GGbuf[k & 1];
        int c = 0;
        for (int i = 0; i < 5; i++)
            for (int j = 0; j <= i; j++) { M[i][j] = base[c]; M[j][i] = base[c]; c++; }
        if (k > 0) {
            int idx = k - 1;
            const double* row = g_GGrow[(k - 1) & 1];
            for (int j = 0; j < 5; j++) { M[idx][j] = row[j]; M[j][idx] = row[j]; }
        }
        if (blockIdx.x == 0) {
            c = 0;
            for (int i = 0; i < 5; i++)
                for (int j = 0; j <= i; j++) g_GGbuf[(k + 1) & 1][c++] = M[i][j];
            for (int j = 0; j < 5; j++) g_GGrow[k & 1][j] = 0.0;   // for spmm(k)
        }
        // float 5x5 solve with partial pivoting: (M + lam I) a = 1
        float A[5][6];
        for (int i = 0; i < 5; i++) {
            for (int j = 0; j < 5; j++) A[i][j] = (float)M[i][j];
            A[i][i] += 1e-4f;
            A[i][5] = 1.f;
        }
        for (int kk = 0; kk < 5; kk++) {
            int piv = kk; float mx = fabsf(A[kk][kk]);
            for (int r = kk + 1; r < 5; r++)
                if (fabsf(A[r][kk]) > mx) { mx = fabsf(A[r][kk]); piv = r; }
            if (piv != kk)
                for (int j = 0; j < 6; j++) { float t = A[kk][j]; A[kk][j] = A[piv][j]; A[piv][j] = t; }
            float inv = 1.f / A[kk][kk];
            for (int r = kk + 1; r < 5; r++) {
                float f = A[r][kk] * inv;
                for (int j = kk; j < 6; j++) A[r][j] -= f * A[kk][j];
            }
        }
        float a[5];
        for (int kk = 4; kk >= 0; kk--) {
            float s = A[kk][5];
            for (int j = kk + 1; j < 5; j++) s -= A[kk][j] * a[j];
            a[kk] = s / A[kk][kk];
        }
        float sum = a[0] + a[1] + a[2] + a[3] + a[4];
        for (int j = 0; j < 5; j++) sa[j] = a[j] / sum;
    }
    __syncthreads();
    float a0 = sa[0], a1 = sa[1], a2 = sa[2], a3 = sa[3], a4 = sa[4];
    int t = blockIdx.x * blockDim.x + threadIdx.x;
    if (t >= NH) return;
    float un = a0 * g_F[0][t] + a1 * g_F[1][t] + a2 * g_F[2][t]
             + a3 * g_F[3][t] + a4 * g_F[4][t];
    g_u[t] = un;
    g_w[t] = 2.f * fmaxf(un, 0.f) - un + g_b[t];
}

// ---------------- decoder: out[n,o] = relu(u[n,:]) @ dec_W[:,o] ----------------
__global__ void k_decode(const float* __restrict__ decW, float* __restrict__ out) {
    __shared__ float Ws[D_HID * D_OUT];   // 4 KB
    for (int i = threadIdx.x; i < D_HID * D_OUT; i += 256) Ws[i] = decW[i];
    __syncthreads();
    int ln = threadIdx.x >> 4;            // 16 nodes / block
    int o  = threadIdx.x & 15;
    int n  = blockIdx.x * 16 + ln;
    if (n >= N_NODES) return;
    float acc = 0.f;
#pragma unroll
    for (int d = 0; d < D_HID; d++)
        acc = fmaf(fmaxf(g_u[n * 64 + d], 0.f), Ws[d * 16 + o], acc);
    out[n * 16 + o] = acc;
}

// ---------------- launch ----------------
extern "C" void kernel_launch(void* const* d_in, const int* in_sizes, int n_in,
                              void* d_out, int out_size) {
    const float* x    = (const float*)d_in[0];
    const int*   ei   = (const int*)  d_in[1];
    const float* ew   = (const float*)d_in[2];
    const float* encW = (const float*)d_in[3];
    const float* encb = (const float*)d_in[4];
    const float* cayB = (const float*)d_in[5];
    const float* decW = (const float*)d_in[6];
    float* out = (float*)d_out;

    const int* src = ei;              // edge_index[0]
    const int* dst = ei + N_EDGES;    // edge_index[1]

    // setup: CSR + Theta + encoder + u0
    k_zero_cnt<<<(N_NODES + 255) / 256, 256>>>();
    k_hist<<<(N_EDGES + 255) / 256, 256>>>(dst);
    k_scan<<<1, 1024>>>();
    k_scatter<<<(N_EDGES + 255) / 256, 256>>>(src, dst, ew);
    k_theta<<<1, 256>>>(cayB);
    k_encode<<<N_NODES / 8, 256>>>(x, encW, encb);
    k_prep0<<<NH / 256, 256>>>();

    // history phase: 5 PR sweeps; spmm epilogue writes u/w for next sweep
    // and accumulates lower-tri Gram pairs (i, j<=i) into g_GGbuf[0]
    for (int i = 0; i < AAM; i++)
        k_spmm<<<N_NODES / 8, 256>>>(i, i + 1, 1, i * (i + 1) / 2, (i < AAM - 1) ? 1 : 0);

    // Anderson phase: combine (merge Gram row + solve + u_new + w), then spmm
    // (last iteration's g() is dead -> its spmm is skipped)
    for (int k = 0; k < AAM; k++) {
        k_combine<<<NH / 256, 256>>>(k);
        if (k < AAM - 1)
            k_spmm<<<N_NODES / 8, 256>>>(k, 5, 0, k & 1, 0);
    }

    k_decode<<<N_NODES / 16, 256>>>(decW, out);
}

// round 3
// speedup vs baseline: 1.6999x; 1.1248x over previous
#include <cuda_runtime.h>

#define N_NODES 10000
#define N_EDGES 320000
#define D_IN    128
#define D_HID   64
#define D_OUT   16
#define NH      (N_NODES * D_HID)
#define AAM     5
#define NGROUPS 1250                 // node groups of 8 (one warp each)
#define GRID_BLOCKS 592              // 148 SMs x 4 blocks guaranteed resident
#define NTHREADS (GRID_BLOCKS * 256)

// ---------------- device scratch ----------------
__device__ float  g_b[NH];
__device__ float  g_u[NH];
__device__ float  g_w[NH];
__device__ float  g_F[AAM][NH];
__device__ float  g_G[AAM][NH];
__device__ float  g_ThT[D_HID * D_HID];   // ThT[k*64+c] = Theta[c][k]
__device__ int    g_rowptr[N_NODES + 1];
__device__ int    g_cur[N_NODES];
__device__ int2   g_edge[N_EDGES];
__device__ double g_GGbuf[2][15];
__device__ double g_GGrow[2][5];
__device__ unsigned          g_bar_cnt;   // zero-init; returns to 0 after each barrier
__device__ volatile unsigned g_bar_gen;   // monotonic across replays

union SmemU {
    struct { float M[64][128]; float fct[64]; } th;   // theta Gauss-Jordan (block 0)
    float2 sTh[D_HID][32];                            // ThT for spmm mix
    int    part[256];                                 // scan partials
};

// ---------------- software grid barrier (all 592 blocks resident) ----------------
__device__ __forceinline__ void gbar() {
    __syncthreads();
    if (threadIdx.x == 0) {
        __threadfence();
        unsigned gen = g_bar_gen;
        if (atomicAdd(&g_bar_cnt, 1u) == GRID_BLOCKS - 1u) {
            g_bar_cnt = 0u;
            __threadfence();
            g_bar_gen = gen + 1u;
        } else {
            while (g_bar_gen == gen) { __nanosleep(64); }
        }
        __threadfence();
    }
    __syncthreads();
}

// ---------------- phase helpers ----------------
__device__ void theta_phase(const float* __restrict__ B, SmemU* su) {
    // block 0 only: Theta = (I+Om)^-1 (I-Om) via Gauss-Jordan (I+Om diag-dominant-ish, no pivot)
    int tid = threadIdx.x;
    for (int idx = tid; idx < 64 * 64; idx += 256) {
        int i = idx >> 6, j = idx & 63;
        float om = 0.5f * (B[i * 64 + j] - B[j * 64 + i]);
        float e  = (i == j) ? 1.f : 0.f;
        su->th.M[i][j]      = e + om;
        su->th.M[i][64 + j] = e - om;
    }
    __syncthreads();
    for (int k = 0; k < 64; k++) {
        float inv = 1.f / su->th.M[k][k];
        __syncthreads();
        for (int j = tid; j < 128; j += 256) su->th.M[k][j] *= inv;
        __syncthreads();
        for (int r = tid; r < 64; r += 256) su->th.fct[r] = su->th.M[r][k];
        __syncthreads();
        for (int idx = tid; idx < 64 * 128; idx += 256) {
            int r = idx >> 7, j = idx & 127;
            if (r != k) su->th.M[r][j] -= su->th.fct[r] * su->th.M[k][j];
        }
        __syncthreads();
    }
    for (int idx = tid; idx < 64 * 64; idx += 256) {
        int k = idx >> 6, c = idx & 63;
        g_ThT[idx] = su->th.M[c][64 + k];
    }
}

__device__ void encode_phase(const float* __restrict__ x, const float* __restrict__ W,
                             const float* __restrict__ bias) {
    int warp = threadIdx.x >> 5, cp = threadIdx.x & 31;
    const float2* __restrict__ W2 = (const float2*)W;
    float2 bsv = ((const float2*)bias)[cp];
    for (int ng = blockIdx.x; ng < NGROUPS; ng += GRID_BLOCKS) {
        int node = ng * 8 + warp;
        const float* __restrict__ xr = x + node * D_IN;
        float2 acc = bsv;
#pragma unroll 16
        for (int k = 0; k < D_IN; k++) {
            float  xk = xr[k];
            float2 w2 = W2[k * 32 + cp];
            acc.x = fmaf(xk, w2.x, acc.x);
            acc.y = fmaf(xk, w2.y, acc.y);
        }
        int row = node * 32 + cp;
        ((float2*)g_b)[row] = acc;
        ((float2*)g_u)[row] = acc;                               // u0 = b
        ((float2*)g_w)[row] = make_float2(2.f * fmaxf(acc.x, 0.f),
                                          2.f * fmaxf(acc.y, 0.f)); // w0 = 2relu(b)
    }
}

// F[slot] = b + 0.5*Theta@spmm(w); G[slot] = F - u; Gram partials dot(G[slot],G[j]) j<npairs
__device__ void spmm_phase(int slot, int npairs, double* target, int write_next,
                           SmemU* su, double (*red)[5]) {
    int warp = threadIdx.x >> 5, lane = threadIdx.x & 31;
    const int2*   __restrict__ eg = g_edge;
    const float2* __restrict__ wv = (const float2*)g_w;
    float p[5];
#pragma unroll
    for (int j = 0; j < 5; j++) p[j] = 0.f;

    for (int ng = blockIdx.x; ng < NGROUPS; ng += GRID_BLOCKS) {
        int node = ng * 8 + warp;
        int beg = g_rowptr[node], end = g_rowptr[node + 1];
        float2 acc = make_float2(0.f, 0.f);
        int e = beg;
        for (; e + 4 <= end; e += 4) {
            int2 e0 = eg[e], e1 = eg[e + 1], e2 = eg[e + 2], e3 = eg[e + 3];
            float2 v0 = wv[e0.x * 32 + lane];
            float2 v1 = wv[e1.x * 32 + lane];
            float2 v2 = wv[e2.x * 32 + lane];
            float2 v3 = wv[e3.x * 32 + lane];
            float w0 = __int_as_float(e0.y), w1 = __int_as_float(e1.y);
            float w2 = __int_as_float(e2.y), w3 = __int_as_float(e3.y);
            acc.x = fmaf(w0, v0.x, acc.x); acc.y = fmaf(w0, v0.y, acc.y);
            acc.x = fmaf(w1, v1.x, acc.x); acc.y = fmaf(w1, v1.y, acc.y);
            acc.x = fmaf(w2, v2.x, acc.x); acc.y = fmaf(w2, v2.y, acc.y);
            acc.x = fmaf(w3, v3.x, acc.x); acc.y = fmaf(w3, v3.y, acc.y);
        }
        for (; e < end; ++e) {
            int2 ed = eg[e];
            float2 v = wv[ed.x * 32 + lane];
            float ww = __int_as_float(ed.y);
            acc.x = fmaf(ww, v.x, acc.x);
            acc.y = fmaf(ww, v.y, acc.y);
        }
        // channel mix via warp shuffles, sTh[k][c'] resident in shared
        float2 o = make_float2(0.f, 0.f);
#pragma unroll
        for (int m = 0; m < 32; ++m) {
            float sx = __shfl_sync(0xffffffffu, acc.x, m);
            float sy = __shfl_sync(0xffffffffu, acc.y, m);
            float2 t0 = su->sTh[2 * m][lane];
            float2 t1 = su->sTh[2 * m + 1][lane];
            o.x = fmaf(t0.x, sx, o.x); o.y = fmaf(t0.y, sx, o.y);
            o.x = fmaf(t1.x, sy, o.x); o.y = fmaf(t1.y, sy, o.y);
        }
        int row = node * 32 + lane;
        float2 bb = ((const float2*)g_b)[row];
        float2 val = make_float2(bb.x + 0.5f * o.x, bb.y + 0.5f * o.y);
        ((float2*)g_F[slot])[row] = val;
        float2 uu = ((const float2*)g_u)[row];
        float2 gn = make_float2(val.x - uu.x, val.y - uu.y);
        ((float2*)g_G[slot])[row] = gn;
        if (write_next) {
            ((float2*)g_u)[row] = val;
            ((float2*)g_w)[row] = make_float2(2.f * fmaxf(val.x, 0.f) - val.x + bb.x,
                                              2.f * fmaxf(val.y, 0.f) - val.y + bb.y);
        }
        for (int j = 0; j < npairs; ++j) {
            float2 gj = (j == slot) ? gn : ((const float2*)g_G[j])[row];
            p[j] = fmaf(gn.x, gj.x, fmaf(gn.y, gj.y, p[j]));
        }
    }
    // one reduction per block per phase
#pragma unroll
    for (int j = 0; j < 5; ++j)
        for (int off = 16; off > 0; off >>= 1)
            p[j] += __shfl_down_sync(0xffffffffu, p[j], off);
    __syncthreads();
    if (lane == 0)
        for (int j = 0; j < 5; ++j) red[warp][j] = (double)p[j];
    __syncthreads();
    if (threadIdx.x < npairs) {
        int j = threadIdx.x;
        double s = red[0][j] + red[1][j] + red[2][j] + red[3][j]
                 + red[4][j] + red[5][j] + red[6][j] + red[7][j];
        atomicAdd(&target[j], s);
    }
}

__device__ void combine_phase(int k, float* sa) {
    if (threadIdx.x == 0) {
        double M[5][5];
        const double* base = g_GGbuf[k & 1];
        int c = 0;
        for (int i = 0; i < 5; i++)
            for (int j = 0; j <= i; j++) { M[i][j] = base[c]; M[j][i] = base[c]; c++; }
        if (k > 0) {
            int idx = k - 1;
            const double* row = g_GGrow[(k - 1) & 1];
            for (int j = 0; j < 5; j++) { M[idx][j] = row[j]; M[j][idx] = row[j]; }
        }
        if (blockIdx.x == 0) {
            c = 0;
            for (int i = 0; i < 5; i++)
                for (int j = 0; j <= i; j++) g_GGbuf[(k + 1) & 1][c++] = M[i][j];
            for (int j = 0; j < 5; j++) g_GGrow[k & 1][j] = 0.0;
        }
        float A[5][6];
        for (int i = 0; i < 5; i++) {
            for (int j = 0; j < 5; j++) A[i][j] = (float)M[i][j];
            A[i][i] += 1e-4f;
            A[i][5] = 1.f;
        }
        for (int kk = 0; kk < 5; kk++) {
            int piv = kk; float mx = fabsf(A[kk][kk]);
            for (int r = kk + 1; r < 5; r++)
                if (fabsf(A[r][kk]) > mx) { mx = fabsf(A[r][kk]); piv = r; }
            if (piv != kk)
                for (int j = 0; j < 6; j++) { float t = A[kk][j]; A[kk][j] = A[piv][j]; A[piv][j] = t; }
            float inv = 1.f / A[kk][kk];
            for (int r = kk + 1; r < 5; r++) {
                float f = A[r][kk] * inv;
                for (int j = kk; j < 6; j++) A[r][j] -= f * A[kk][j];
            }
        }
        float a[5];
        for (int kk = 4; kk >= 0; kk--) {
            float s = A[kk][5];
            for (int j = kk + 1; j < 5; j++) s -= A[kk][j] * a[j];
            a[kk] = s / A[kk][kk];
        }
        float sum = a[0] + a[1] + a[2] + a[3] + a[4];
        for (int j = 0; j < 5; j++) sa[j] = a[j] / sum;
    }
    __syncthreads();
    float a0 = sa[0], a1 = sa[1], a2 = sa[2], a3 = sa[3], a4 = sa[4];
    const float2* F0 = (const float2*)g_F[0];
    const float2* F1 = (const float2*)g_F[1];
    const float2* F2 = (const float2*)g_F[2];
    const float2* F3 = (const float2*)g_F[3];
    const float2* F4 = (const float2*)g_F[4];
    for (int ng = blockIdx.x; ng < NGROUPS; ng += GRID_BLOCKS) {
        int idx = ng * 256 + threadIdx.x;
        float2 f0 = F0[idx], f1 = F1[idx], f2 = F2[idx], f3 = F3[idx], f4 = F4[idx];
        float2 un;
        un.x = a0 * f0.x + a1 * f1.x + a2 * f2.x + a3 * f3.x + a4 * f4.x;
        un.y = a0 * f0.y + a1 * f1.y + a2 * f2.y + a3 * f3.y + a4 * f4.y;
        ((float2*)g_u)[idx] = un;
        float2 bb = ((const float2*)g_b)[idx];
        ((float2*)g_w)[idx] = make_float2(2.f * fmaxf(un.x, 0.f) - un.x + bb.x,
                                          2.f * fmaxf(un.y, 0.f) - un.y + bb.y);
    }
}

__device__ void decode_phase(const float* __restrict__ decW, float* __restrict__ out) {
    int warp = threadIdx.x >> 5, lane = threadIdx.x & 31;
    int o = lane & 15;
    int half = lane >> 4;   // 0: d in [0,32), 1: d in [32,64)
    for (int ng = blockIdx.x; ng < NGROUPS; ng += GRID_BLOCKS) {
        int node = ng * 8 + warp;
        const float* __restrict__ ur = g_u + node * 64 + half * 32;
        float acc = 0.f;
#pragma unroll
        for (int d = 0; d < 32; d++)
            acc = fmaf(fmaxf(ur[d], 0.f), decW[(half * 32 + d) * 16 + o], acc);
        acc += __shfl_down_sync(0xffffffffu, acc, 16);
        if (half == 0) out[node * 16 + o] = acc;
    }
}

// ---------------- the single persistent kernel ----------------
__global__ void __launch_bounds__(256, 4) k_mega(
    const float* __restrict__ x, const int* __restrict__ ei,
    const float* __restrict__ ew, const float* __restrict__ encW,
    const float* __restrict__ encb, const float* __restrict__ cayB,
    const float* __restrict__ decW, float* __restrict__ out)
{
    __shared__ SmemU su;
    __shared__ double red[8][5];
    __shared__ float sa[5];

    const int* src = ei;
    const int* dst = ei + N_EDGES;
    int gtid = blockIdx.x * 256 + threadIdx.x;

    // A: zero counters + Gram buf
    for (int i = gtid; i < N_NODES; i += NTHREADS) g_cur[i] = 0;
    if (gtid < 15) g_GGbuf[0][gtid] = 0.0;
    gbar();

    // B: degree histogram
    for (int e = gtid; e < N_EDGES; e += NTHREADS) atomicAdd(&g_cur[dst[e]], 1);
    gbar();

    // C: prefix scan (block 0, 256 threads, 40 nodes/thread)
    if (blockIdx.x == 0) {
        int t = threadIdx.x;
        int beg = t * 40, end = beg + 40; if (end > N_NODES) end = N_NODES;
        int s = 0;
        for (int i = beg; i < end; i++) s += g_cur[i];
        su.part[t] = s;
        __syncthreads();
        for (int d = 1; d < 256; d <<= 1) {
            int v = (t >= d) ? su.part[t - d] : 0;
            __syncthreads();
            su.part[t] += v;
            __syncthreads();
        }
        int off = (t > 0) ? su.part[t - 1] : 0;
        for (int i = beg; i < end; i++) {
            int c = g_cur[i];
            g_rowptr[i] = off;
            g_cur[i]    = off;
            off += c;
        }
        if (t == 0) g_rowptr[N_NODES] = N_EDGES;
    }
    gbar();

    // D: CSR scatter
    for (int e = gtid; e < N_EDGES; e += NTHREADS) {
        int d = dst[e];
        int p = atomicAdd(&g_cur[d], 1);
        g_edge[p] = make_int2(src[e], __float_as_int(ew[e]));
    }
    gbar();

    // E: theta (block 0) + encoder/u0/w0 (all blocks)
    encode_phase(x, encW, encb);
    if (blockIdx.x == 0) { __syncthreads(); theta_phase(cayB, &su); }
    gbar();

    // load ThT into shared once, reused by all 9 spmm phases
    for (int i = threadIdx.x; i < D_HID * 32; i += 256)
        ((float2*)su.sTh)[i] = ((const float2*)g_ThT)[i];
    __syncthreads();

    // history: 5 PR sweeps, Gram lower-tri into GGbuf[0]
    for (int i = 0; i < AAM; i++) {
        spmm_phase(i, i + 1, &g_GGbuf[0][i * (i + 1) / 2], (i < AAM - 1) ? 1 : 0, &su, red);
        gbar();
    }

    // Anderson: combine -> spmm (last g() dead, skipped)
    for (int k = 0; k < AAM; k++) {
        combine_phase(k, sa);
        if (k < AAM - 1) {
            gbar();
            spmm_phase(k, 5, g_GGrow[k & 1], 0, &su, red);
            gbar();
        }
    }

    // decode: same-block node ownership -> only block-local sync needed
    __syncthreads();
    decode_phase(decW, out);
}

// ---------------- launch: ONE kernel ----------------
extern "C" void kernel_launch(void* const* d_in, const int* in_sizes, int n_in,
                              void* d_out, int out_size) {
    const float* x    = (const float*)d_in[0];
    const int*   ei   = (const int*)  d_in[1];
    const float* ew   = (const float*)d_in[2];
    const float* encW = (const float*)d_in[3];
    const float* encb = (const float*)d_in[4];
    const float* cayB = (const float*)d_in[5];
    const float* decW = (const float*)d_in[6];
    float* out = (float*)d_out;

    k_mega<<<GRID_BLOCKS, 256>>>(x, ei, ew, encW, encb, cayB, decW, out);
}

// round 4
// speedup vs baseline: 1.7452x; 1.0267x over previous
#include <cuda_runtime.h>

#define N_NODES 10000
#define N_EDGES 320000
#define D_IN    128
#define D_HID   64
#define D_OUT   16
#define NH      (N_NODES * D_HID)
#define AAM     5
#define TPB         512
#define GRID_BLOCKS 296              // 148 SMs x 2 blocks guaranteed resident
#define NWARPS      (GRID_BLOCKS * (TPB / 32))   // 4736
#define NTHREADS    (GRID_BLOCKS * TPB)

typedef unsigned long long ull;

// ---------------- device scratch ----------------
__device__ float  g_b[NH];
__device__ float  g_u[NH];
__device__ float  g_wbuf[2][NH];          // ping-pong SPMM input
__device__ float  g_F[AAM][NH];
__device__ float  g_G[AAM][NH];
__device__ float  g_ThT[D_HID * D_HID];   // ThT[k*64+c] = Theta[c][k]
__device__ int    g_rowptr[N_NODES + 1];
__device__ int    g_cur[N_NODES];
__device__ int2   g_edge[N_EDGES];
__device__ double g_GGbuf[2][15];
__device__ double g_GGrow[2][5];
__device__ int    g_tick[12];             // per-phase dynamic work counters
__device__ unsigned          g_bar_cnt;
__device__ volatile unsigned g_bar_gen;

union SmemU {
    struct { float M[64][128]; float fct[64]; } th;   // Cayley Gauss-Jordan
    ull  sThU[D_HID][32];                              // packed Theta pairs for mix
    int  part[TPB];                                    // scan partials
};

// ---------------- f32x2 helpers (sm_103a packed fma) ----------------
__device__ __forceinline__ void fma2(ull& d, ull a, ull b) {
    asm("fma.rn.f32x2 %0, %1, %2, %0;" : "+l"(d) : "l"(a), "l"(b));
}
__device__ __forceinline__ ull splat2(float s) {
    ull r; asm("mov.b64 %0, {%1, %1};" : "=l"(r) : "f"(s)); return r;
}
__device__ __forceinline__ float2 unpack2(ull v) {
    float2 r; asm("mov.b64 {%0, %1}, %2;" : "=f"(r.x), "=f"(r.y) : "l"(v)); return r;
}

// ---------------- software grid barrier (all 296 blocks resident) ----------------
__device__ __forceinline__ void gbar() {
    __syncthreads();
    if (threadIdx.x == 0) {
        __threadfence();
        unsigned gen = g_bar_gen;
        if (atomicAdd(&g_bar_cnt, 1u) == GRID_BLOCKS - 1u) {
            g_bar_cnt = 0u;
            __threadfence();
            g_bar_gen = gen + 1u;
        } else {
            while (g_bar_gen == gen) { __nanosleep(64); }
        }
        __threadfence();
    }
    __syncthreads();
}

// ---------------- Cayley: Theta = (I+Om)^-1 (I-Om) ----------------
__device__ void theta_phase(const float* __restrict__ B, SmemU* su) {
    int tid = threadIdx.x;
    for (int idx = tid; idx < 64 * 64; idx += TPB) {
        int i = idx >> 6, j = idx & 63;
        float om = 0.5f * (B[i * 64 + j] - B[j * 64 + i]);
        float e  = (i == j) ? 1.f : 0.f;
        su->th.M[i][j]      = e + om;
        su->th.M[i][64 + j] = e - om;
    }
    __syncthreads();
    for (int k = 0; k < 64; k++) {
        float inv = 1.f / su->th.M[k][k];
        __syncthreads();
        for (int j = tid; j < 128; j += TPB) su->th.M[k][j] *= inv;
        __syncthreads();
        for (int r = tid; r < 64; r += TPB) su->th.fct[r] = su->th.M[r][k];
        __syncthreads();
        for (int idx = tid; idx < 64 * 128; idx += TPB) {
            int r = idx >> 7, j = idx & 127;
            if (r != k) su->th.M[r][j] -= su->th.fct[r] * su->th.M[k][j];
        }
        __syncthreads();
    }
    for (int idx = tid; idx < 64 * 64; idx += TPB) {
        int k = idx >> 6, c = idx & 63;
        g_ThT[idx] = su->th.M[c][64 + k];
    }
}

// ---------------- encoder + u0/w0 ----------------
__device__ void encode_phase(const float* __restrict__ x, const float* __restrict__ W,
                             const float* __restrict__ bias) {
    int warp = threadIdx.x >> 5, cp = threadIdx.x & 31;
    int g = blockIdx.x * (TPB / 32) + warp;
    const float2* __restrict__ W2 = (const float2*)W;
    float2 bsv = ((const float2*)bias)[cp];
    for (int node = g; node < N_NODES; node += NWARPS) {
        const float* __restrict__ xr = x + node * D_IN;
        float2 acc = bsv;
#pragma unroll 16
        for (int k = 0; k < D_IN; k++) {
            float  xk = xr[k];
            float2 w2 = W2[k * 32 + cp];
            acc.x = fmaf(xk, w2.x, acc.x);
            acc.y = fmaf(xk, w2.y, acc.y);
        }
        int row = node * 32 + cp;
        ((float2*)g_b)[row] = acc;
        ((float2*)g_u)[row] = acc;                                  // u0 = b
        ((float2*)g_wbuf[0])[row] = make_float2(2.f * fmaxf(acc.x, 0.f),
                                                2.f * fmaxf(acc.y, 0.f));
    }
}

// ---------------- fused SPMM + mix + G + Gram partials (+ next-u/w) ----------------
__device__ void spmm_phase(int ph, int slot, int npairs, double* target, int wr_next,
                           const float* __restrict__ wsrc, float* __restrict__ wdst,
                           SmemU* su, double (*red)[5]) {
    int warp = threadIdx.x >> 5, lane = threadIdx.x & 31;
    const int2*   __restrict__ eg = g_edge;
    const float2* __restrict__ wv = (const float2*)wsrc;
    float p[5];
#pragma unroll
    for (int j = 0; j < 5; j++) p[j] = 0.f;

    int node;
    if (lane == 0) node = atomicAdd(&g_tick[ph], 1);
    node = __shfl_sync(0xffffffffu, node, 0);

    while (node < N_NODES) {
        int beg = g_rowptr[node], end = g_rowptr[node + 1];
        float2 a0 = make_float2(0.f, 0.f), a1 = make_float2(0.f, 0.f);
        int e = beg;
        for (; e + 8 <= end; e += 8) {
            int2 ed[8]; float2 v[8];
#pragma unroll
            for (int i = 0; i < 8; i++) ed[i] = eg[e + i];
#pragma unroll
            for (int i = 0; i < 8; i++) v[i] = wv[ed[i].x * 32 + lane];
#pragma unroll
            for (int i = 0; i < 8; i++) {
                float ww = __int_as_float(ed[i].y);
                if (i & 1) { a1.x = fmaf(ww, v[i].x, a1.x); a1.y = fmaf(ww, v[i].y, a1.y); }
                else       { a0.x = fmaf(ww, v[i].x, a0.x); a0.y = fmaf(ww, v[i].y, a0.y); }
            }
        }
        for (; e < end; ++e) {
            int2 ed = eg[e];
            float2 v = wv[ed.x * 32 + lane];
            float ww = __int_as_float(ed.y);
            a0.x = fmaf(ww, v.x, a0.x); a0.y = fmaf(ww, v.y, a0.y);
        }
        float2 acc = make_float2(a0.x + a1.x, a0.y + a1.y);

        // channel mix: packed f32x2 FMA, Theta pairs from shared
        ull o = 0ull;
#pragma unroll
        for (int m = 0; m < 32; ++m) {
            float sx = __shfl_sync(0xffffffffu, acc.x, m);   // s[2m]
            float sy = __shfl_sync(0xffffffffu, acc.y, m);   // s[2m+1]
            ull t0 = su->sThU[2 * m][lane];
            ull t1 = su->sThU[2 * m + 1][lane];
            fma2(o, t0, splat2(sx));
            fma2(o, t1, splat2(sy));
        }
        float2 mix = unpack2(o);

        int row = node * 32 + lane;
        float2 bb = ((const float2*)g_b)[row];
        float2 val = make_float2(bb.x + 0.5f * mix.x, bb.y + 0.5f * mix.y);
        ((float2*)g_F[slot])[row] = val;
        float2 uu = ((const float2*)g_u)[row];
        float2 gn = make_float2(val.x - uu.x, val.y - uu.y);
        ((float2*)g_G[slot])[row] = gn;
        if (wr_next) {
            ((float2*)g_u)[row] = val;
            ((float2*)wdst)[row] = make_float2(2.f * fmaxf(val.x, 0.f) - val.x + bb.x,
                                               2.f * fmaxf(val.y, 0.f) - val.y + bb.y);
        }
        for (int j = 0; j < npairs; ++j) {
            float2 gj = (j == slot) ? gn : ((const float2*)g_G[j])[row];
            p[j] = fmaf(gn.x, gj.x, fmaf(gn.y, gj.y, p[j]));
        }

        if (lane == 0) node = atomicAdd(&g_tick[ph], 1);
        node = __shfl_sync(0xffffffffu, node, 0);
    }

#pragma unroll
    for (int j = 0; j < 5; ++j)
        for (int off = 16; off > 0; off >>= 1)
            p[j] += __shfl_down_sync(0xffffffffu, p[j], off);
    __syncthreads();
    if (lane == 0)
        for (int j = 0; j < 5; ++j) red[warp][j] = (double)p[j];
    __syncthreads();
    if (threadIdx.x < npairs) {
        int j = threadIdx.x;
        double s = 0.0;
        for (int w = 0; w < TPB / 32; w++) s += red[w][j];
        atomicAdd(&target[j], s);
    }
}

// ---------------- combine(k): Gram merge + 5x5 solve + u_new (+ fused decode at k=4) ----------------
__device__ void combine_phase(int k, float* sa, const float* __restrict__ decW,
                              float* __restrict__ out) {
    if (threadIdx.x == 0) {
        double M[5][5];
        const double* base = g_GGbuf[k & 1];
        int c = 0;
        for (int i = 0; i < 5; i++)
            for (int j = 0; j <= i; j++) { M[i][j] = base[c]; M[j][i] = base[c]; c++; }
        if (k > 0) {
            int idx = k - 1;
            const double* row = g_GGrow[(k - 1) & 1];
            for (int j = 0; j < 5; j++) { M[idx][j] = row[j]; M[j][idx] = row[j]; }
        }
        if (blockIdx.x == 0 && k < AAM - 1) {
            c = 0;
            for (int i = 0; i < 5; i++)
                for (int j = 0; j <= i; j++) g_GGbuf[(k + 1) & 1][c++] = M[i][j];
            for (int j = 0; j < 5; j++) g_GGrow[k & 1][j] = 0.0;
        }
        float A[5][6];
        for (int i = 0; i < 5; i++) {
            for (int j = 0; j < 5; j++) A[i][j] = (float)M[i][j];
            A[i][i] += 1e-4f;
            A[i][5] = 1.f;
        }
        for (int kk = 0; kk < 5; kk++) {
            int piv = kk; float mx = fabsf(A[kk][kk]);
            for (int r = kk + 1; r < 5; r++)
                if (fabsf(A[r][kk]) > mx) { mx = fabsf(A[r][kk]); piv = r; }
            if (piv != kk)
                for (int j = 0; j < 6; j++) { float t = A[kk][j]; A[kk][j] = A[piv][j]; A[piv][j] = t; }
            float inv = 1.f / A[kk][kk];
            for (int r = kk + 1; r < 5; r++) {
                float f = A[r][kk] * inv;
                for (int j = kk; j < 6; j++) A[r][j] -= f * A[kk][j];
            }
        }
        float a[5];
        for (int kk = 4; kk >= 0; kk--) {
            float s = A[kk][5];
            for (int j = kk + 1; j < 5; j++) s -= A[kk][j] * a[j];
            a[kk] = s / A[kk][kk];
        }
        float sum = a[0] + a[1] + a[2] + a[3] + a[4];
        for (int j = 0; j < 5; j++) sa[j] = a[j] / sum;
    }
    __syncthreads();
    float a0 = sa[0], a1 = sa[1], a2 = sa[2], a3 = sa[3], a4 = sa[4];

    int warp = threadIdx.x >> 5, lane = threadIdx.x & 31;
    int g = blockIdx.x * (TPB / 32) + warp;
    const float2* F0 = (const float2*)g_F[0];
    const float2* F1 = (const float2*)g_F[1];
    const float2* F2 = (const float2*)g_F[2];
    const float2* F3 = (const float2*)g_F[3];
    const float2* F4 = (const float2*)g_F[4];
    for (int node = g; node < N_NODES; node += NWARPS) {
        int idx = node * 32 + lane;
        float2 f0 = F0[idx], f1 = F1[idx], f2 = F2[idx], f3 = F3[idx], f4 = F4[idx];
        float2 un;
        un.x = a0 * f0.x + a1 * f1.x + a2 * f2.x + a3 * f3.x + a4 * f4.x;
        un.y = a0 * f0.y + a1 * f1.y + a2 * f2.y + a3 * f3.y + a4 * f4.y;
        if (k < AAM - 1) {
            ((float2*)g_u)[idx] = un;
            float2 bb = ((const float2*)g_b)[idx];
            ((float2*)g_wbuf[0])[idx] =
                make_float2(2.f * fmaxf(un.x, 0.f) - un.x + bb.x,
                            2.f * fmaxf(un.y, 0.f) - un.y + bb.y);
        } else {
            // fused decode: warp owns node's u in registers, no barrier needed
            float rx = fmaxf(un.x, 0.f), ry = fmaxf(un.y, 0.f);
            int o = lane & 15, half = lane >> 4;
            float acc = 0.f;
#pragma unroll
            for (int i = 0; i < 16; i++) {
                int m = half * 16 + i;
                float sx = __shfl_sync(0xffffffffu, rx, m);   // relu(u[2m])
                float sy = __shfl_sync(0xffffffffu, ry, m);   // relu(u[2m+1])
                acc = fmaf(sx, decW[(2 * m) * 16 + o], acc);
                acc = fmaf(sy, decW[(2 * m + 1) * 16 + o], acc);
            }
            acc += __shfl_down_sync(0xffffffffu, acc, 16);
            if (half == 0) out[node * 16 + o] = acc;
        }
    }
}

// ---------------- the single persistent kernel ----------------
__global__ void __launch_bounds__(TPB, 2) k_mega(
    const float* __restrict__ x, const int* __restrict__ ei,
    const float* __restrict__ ew, const float* __restrict__ encW,
    const float* __restrict__ encb, const float* __restrict__ cayB,
    const float* __restrict__ decW, float* __restrict__ out)
{
    __shared__ SmemU su;
    __shared__ double red[TPB / 32][5];
    __shared__ float sa[5];

    const int* src = ei;
    const int* dst = ei + N_EDGES;
    int gtid = blockIdx.x * TPB + threadIdx.x;

    // A: zero counters, Gram buf, tickets
    for (int i = gtid; i < N_NODES; i += NTHREADS) g_cur[i] = 0;
    if (gtid < 15) g_GGbuf[0][gtid] = 0.0;
    if (gtid < 12) g_tick[gtid] = 0;
    gbar();

    // B: degree histogram (edges)  ||  encoder + u0/w0 (nodes)  — independent
    for (int e = gtid; e < N_EDGES; e += NTHREADS) atomicAdd(&g_cur[dst[e]], 1);
    encode_phase(x, encW, encb);
    gbar();

    // C: prefix scan (block 0)  ||  Cayley theta (block 1)
    if (blockIdx.x == 0) {
        int t = threadIdx.x;
        const int CH = (N_NODES + TPB - 1) / TPB;   // 20
        int beg = t * CH, end = beg + CH; if (end > N_NODES) end = N_NODES;
        int s = 0;
        for (int i = beg; i < end; i++) s += g_cur[i];
        su.part[t] = s;
        __syncthreads();
        for (int d = 1; d < TPB; d <<= 1) {
            int v = (t >= d) ? su.part[t - d] : 0;
            __syncthreads();
            su.part[t] += v;
            __syncthreads();
        }
        int off = (t > 0) ? su.part[t - 1] : 0;
        for (int i = beg; i < end; i++) {
            int c = g_cur[i];
            g_rowptr[i] = off;
            g_cur[i]    = off;
            off += c;
        }
        if (t == 0) g_rowptr[N_NODES] = N_EDGES;
    } else if (blockIdx.x == 1) {
        theta_phase(cayB, &su);
    }
    gbar();

    // D: CSR scatter + stage packed Theta into shared (reused by all 9 spmm phases)
    for (int e = gtid; e < N_EDGES; e += NTHREADS) {
        int d = dst[e];
        int p = atomicAdd(&g_cur[d], 1);
        g_edge[p] = make_int2(src[e], __float_as_int(ew[e]));
    }
    for (int i = threadIdx.x; i < D_HID * 32; i += TPB)
        ((ull*)su.sThU)[i] = ((const ull*)g_ThT)[i];
    gbar();

    // history: 5 PR sweeps (w ping-pong), Gram lower-tri into GGbuf[0]
    for (int i = 0; i < AAM; i++) {
        spmm_phase(i, i, i + 1, &g_GGbuf[0][i * (i + 1) / 2], (i < AAM - 1) ? 1 : 0,
                   g_wbuf[i & 1], g_wbuf[(i + 1) & 1], &su, red);
        gbar();
    }

    // Anderson: combine -> spmm (last g() dead); final combine fuses decode
    for (int k = 0; k < AAM; k++) {
        combine_phase(k, sa, decW, out);
        if (k < AAM - 1) {
            gbar();
            spmm_phase(5 + k, k, 5, g_GGrow[k & 1], 0, g_wbuf[0], 0, &su, red);
            gbar();
        }
    }
}

// ---------------- launch: ONE kernel ----------------
extern "C" void kernel_launch(void* const* d_in, const int* in_sizes, int n_in,
                              void* d_out, int out_size) {
    const float* x    = (const float*)d_in[0];
    const int*   ei   = (const int*)  d_in[1];
    const float* ew   = (const float*)d_in[2];
    const float* encW = (const float*)d_in[3];
    const float* encb = (const float*)d_in[4];
    const float* cayB = (const float*)d_in[5];
    const float* decW = (const float*)d_in[6];
    float* out = (float*)d_out;

    k_mega<<<GRID_BLOCKS, TPB>>>(x, ei, ew, encW, encb, cayB, decW, out);
}

// round 5
// speedup vs baseline: 1.8755x; 1.0746x over previous
#include <cuda_runtime.h>

#define N_NODES 10000
#define N_EDGES 320000
#define D_IN    128
#define D_HID   64
#define D_OUT   16
#define NH      (N_NODES * D_HID)
#define AAM     5
#define TPB         512
#define GRID_BLOCKS 296              // 148 SMs x 2 blocks guaranteed resident
#define NWARPS      (GRID_BLOCKS * (TPB / 32))   // 4736
#define NTHREADS    (GRID_BLOCKS * TPB)
#define COST_TOTAL  (N_EDGES + 16 * N_NODES)     // 480000 (node fixed-cost = 16 edges)

typedef unsigned long long ull;

// ---------------- device scratch ----------------
__device__ float  g_b[NH];
__device__ float  g_u[NH];
__device__ float  g_wbuf[2][NH];          // ping-pong SPMM input
__device__ float  g_F[AAM][NH];
__device__ float  g_G[AAM][NH];
__device__ float  g_ThT[D_HID * D_HID];   // ThT[k*64+c] = Theta[c][k]
__device__ int    g_rowptr[N_NODES + 1];
__device__ int    g_cur[N_NODES];
__device__ int2   g_edge[N_EDGES];
__device__ int    g_wstart[NWARPS + 1];   // per-warp balanced node ranges
__device__ double g_GGbuf[2][15];
__device__ double g_GGrow[2][5];
__device__ unsigned          g_bar_cnt;
__device__ volatile unsigned g_bar_gen;

union SmemU {
    struct { float M[64][128]; float fct[64]; } th;
    ull  sThU[D_HID][32];                 // packed Theta pairs for mix
    int  part[TPB];
};

// ---------------- f32x2 helpers ----------------
__device__ __forceinline__ void fma2(ull& d, ull a, ull b) {
    asm("fma.rn.f32x2 %0, %1, %2, %0;" : "+l"(d) : "l"(a), "l"(b));
}
__device__ __forceinline__ ull splat2(float s) {
    ull r; asm("mov.b64 %0, {%1, %1};" : "=l"(r) : "f"(s)); return r;
}
__device__ __forceinline__ float2 unpack2(ull v) {
    float2 r; asm("mov.b64 {%0, %1}, %2;" : "=f"(r.x), "=f"(r.y) : "l"(v)); return r;
}

// ---------------- software grid barrier ----------------
__device__ __forceinline__ void gbar() {
    __syncthreads();
    if (threadIdx.x == 0) {
        __threadfence();
        unsigned gen = g_bar_gen;
        if (atomicAdd(&g_bar_cnt, 1u) == GRID_BLOCKS - 1u) {
            g_bar_cnt = 0u;
            __threadfence();
            g_bar_gen = gen + 1u;
        } else {
            while (g_bar_gen == gen) { __nanosleep(64); }
        }
        __threadfence();
    }
    __syncthreads();
}

// ---------------- Cayley: Theta = (I+Om)^-1 (I-Om) ----------------
__device__ void theta_phase(const float* __restrict__ B, SmemU* su) {
    int tid = threadIdx.x;
    for (int idx = tid; idx < 64 * 64; idx += TPB) {
        int i = idx >> 6, j = idx & 63;
        float om = 0.5f * (B[i * 64 + j] - B[j * 64 + i]);
        float e  = (i == j) ? 1.f : 0.f;
        su->th.M[i][j]      = e + om;
        su->th.M[i][64 + j] = e - om;
    }
    __syncthreads();
    for (int k = 0; k < 64; k++) {
        float inv = 1.f / su->th.M[k][k];
        __syncthreads();
        for (int j = tid; j < 128; j += TPB) su->th.M[k][j] *= inv;
        __syncthreads();
        for (int r = tid; r < 64; r += TPB) su->th.fct[r] = su->th.M[r][k];
        __syncthreads();
        for (int idx = tid; idx < 64 * 128; idx += TPB) {
            int r = idx >> 7, j = idx & 127;
            if (r != k) su->th.M[r][j] -= su->th.fct[r] * su->th.M[k][j];
        }
        __syncthreads();
    }
    for (int idx = tid; idx < 64 * 64; idx += TPB) {
        int k = idx >> 6, c = idx & 63;
        g_ThT[idx] = su->th.M[c][64 + k];
    }
}

// ---------------- encoder + u0/w0 ----------------
__device__ void encode_phase(const float* __restrict__ x, const float* __restrict__ W,
                             const float* __restrict__ bias) {
    int warp = threadIdx.x >> 5, cp = threadIdx.x & 31;
    int g = blockIdx.x * (TPB / 32) + warp;
    const float2* __restrict__ W2 = (const float2*)W;
    float2 bsv = ((const float2*)bias)[cp];
    for (int node = g; node < N_NODES; node += NWARPS) {
        const float* __restrict__ xr = x + node * D_IN;
        float2 acc = bsv;
#pragma unroll 16
        for (int k = 0; k < D_IN; k++) {
            float  xk = xr[k];
            float2 w2 = W2[k * 32 + cp];
            acc.x = fmaf(xk, w2.x, acc.x);
            acc.y = fmaf(xk, w2.y, acc.y);
        }
        int row = node * 32 + cp;
        ((float2*)g_b)[row] = acc;
        ((float2*)g_u)[row] = acc;
        ((float2*)g_wbuf[0])[row] = make_float2(2.f * fmaxf(acc.x, 0.f),
                                                2.f * fmaxf(acc.y, 0.f));
    }
}

// ---------------- gather one node's weighted neighbor sum ----------------
__device__ __forceinline__ float2 gather(const int2* __restrict__ eg,
                                         const float2* __restrict__ wv,
                                         int beg, int end, int lane) {
    float2 a0 = make_float2(0.f, 0.f), a1 = make_float2(0.f, 0.f);
    float2 a2 = make_float2(0.f, 0.f), a3 = make_float2(0.f, 0.f);
    int e = beg;
    for (; e + 8 <= end; e += 8) {
        int2 d0 = eg[e],     d1 = eg[e + 1], d2 = eg[e + 2], d3 = eg[e + 3];
        int2 d4 = eg[e + 4], d5 = eg[e + 5], d6 = eg[e + 6], d7 = eg[e + 7];
        float2 v0 = wv[d0.x * 32 + lane], v1 = wv[d1.x * 32 + lane];
        float2 v2 = wv[d2.x * 32 + lane], v3 = wv[d3.x * 32 + lane];
        float2 v4 = wv[d4.x * 32 + lane], v5 = wv[d5.x * 32 + lane];
        float2 v6 = wv[d6.x * 32 + lane], v7 = wv[d7.x * 32 + lane];
        float w0 = __int_as_float(d0.y), w1 = __int_as_float(d1.y);
        float w2 = __int_as_float(d2.y), w3 = __int_as_float(d3.y);
        float w4 = __int_as_float(d4.y), w5 = __int_as_float(d5.y);
        float w6 = __int_as_float(d6.y), w7 = __int_as_float(d7.y);
        a0.x = fmaf(w0, v0.x, a0.x); a0.y = fmaf(w0, v0.y, a0.y);
        a1.x = fmaf(w1, v1.x, a1.x); a1.y = fmaf(w1, v1.y, a1.y);
        a2.x = fmaf(w2, v2.x, a2.x); a2.y = fmaf(w2, v2.y, a2.y);
        a3.x = fmaf(w3, v3.x, a3.x); a3.y = fmaf(w3, v3.y, a3.y);
        a0.x = fmaf(w4, v4.x, a0.x); a0.y = fmaf(w4, v4.y, a0.y);
        a1.x = fmaf(w5, v5.x, a1.x); a1.y = fmaf(w5, v5.y, a1.y);
        a2.x = fmaf(w6, v6.x, a2.x); a2.y = fmaf(w6, v6.y, a2.y);
        a3.x = fmaf(w7, v7.x, a3.x); a3.y = fmaf(w7, v7.y, a3.y);
    }
    for (; e < end; ++e) {
        int2 ed = eg[e];
        float2 v = wv[ed.x * 32 + lane];
        float ww = __int_as_float(ed.y);
        a0.x = fmaf(ww, v.x, a0.x); a0.y = fmaf(ww, v.y, a0.y);
    }
    return make_float2(a0.x + a1.x + a2.x + a3.x, a0.y + a1.y + a2.y + a3.y);
}

// ---------------- per-node epilogue: F, G, Gram partials, optional next u/w ----------------
__device__ __forceinline__ void epilogue(int node, int lane, float2 mix, int slot,
                                         int npairs, int wr_next, float* __restrict__ wdst,
                                         float* p) {
    int row = node * 32 + lane;
    float2 bb = ((const float2*)g_b)[row];
    float2 uu = ((const float2*)g_u)[row];
    float2 val = make_float2(bb.x + 0.5f * mix.x, bb.y + 0.5f * mix.y);
    ((float2*)g_F[slot])[row] = val;
    float2 gn = make_float2(val.x - uu.x, val.y - uu.y);
    ((float2*)g_G[slot])[row] = gn;
    if (wr_next) {
        ((float2*)g_u)[row] = val;
        ((float2*)wdst)[row] = make_float2(2.f * fmaxf(val.x, 0.f) - val.x + bb.x,
                                           2.f * fmaxf(val.y, 0.f) - val.y + bb.y);
    }
    for (int j = 0; j < npairs; ++j) {
        float2 gj = (j == slot) ? gn : ((const float2*)g_G[j])[row];
        p[j] = fmaf(gn.x, gj.x, fmaf(gn.y, gj.y, p[j]));
    }
}

// ---------------- fused SPMM + mix + G + Gram partials ----------------
__device__ void spmm_phase(int slot, int npairs, double* target, int wr_next,
                           const float* __restrict__ wsrc, float* __restrict__ wdst,
                           SmemU* su, double (*red)[5]) {
    int warp = threadIdx.x >> 5, lane = threadIdx.x & 31;
    int w = blockIdx.x * (TPB / 32) + warp;
    const int2*   __restrict__ eg = g_edge;
    const float2* __restrict__ wv = (const float2*)wsrc;
    float p[5];
#pragma unroll
    for (int j = 0; j < 5; j++) p[j] = 0.f;

    int n = g_wstart[w], ne = g_wstart[w + 1];

    // pairs: shared Theta-row LDS, interleaved epilogues
    for (; n + 1 < ne; n += 2) {
        int r0 = g_rowptr[n], r1 = g_rowptr[n + 1], r2 = g_rowptr[n + 2];
        float2 accA = gather(eg, wv, r0, r1, lane);
        float2 accB = gather(eg, wv, r1, r2, lane);
        ull oA0 = 0ull, oA1 = 0ull, oB0 = 0ull, oB1 = 0ull;
#pragma unroll
        for (int m = 0; m < 32; ++m) {
            ull t0 = su->sThU[2 * m][lane];
            ull t1 = su->sThU[2 * m + 1][lane];
            fma2(oA0, t0, splat2(__shfl_sync(0xffffffffu, accA.x, m)));
            fma2(oA1, t1, splat2(__shfl_sync(0xffffffffu, accA.y, m)));
            fma2(oB0, t0, splat2(__shfl_sync(0xffffffffu, accB.x, m)));
            fma2(oB1, t1, splat2(__shfl_sync(0xffffffffu, accB.y, m)));
        }
        float2 mA0 = unpack2(oA0), mA1 = unpack2(oA1);
        float2 mB0 = unpack2(oB0), mB1 = unpack2(oB1);
        epilogue(n,     lane, make_float2(mA0.x + mA1.x, mA0.y + mA1.y),
                 slot, npairs, wr_next, wdst, p);
        epilogue(n + 1, lane, make_float2(mB0.x + mB1.x, mB0.y + mB1.y),
                 slot, npairs, wr_next, wdst, p);
    }
    // tail single node
    if (n < ne) {
        int r0 = g_rowptr[n], r1 = g_rowptr[n + 1];
        float2 acc = gather(eg, wv, r0, r1, lane);
        ull o0 = 0ull, o1 = 0ull;
#pragma unroll
        for (int m = 0; m < 32; ++m) {
            ull t0 = su->sThU[2 * m][lane];
            ull t1 = su->sThU[2 * m + 1][lane];
            fma2(o0, t0, splat2(__shfl_sync(0xffffffffu, acc.x, m)));
            fma2(o1, t1, splat2(__shfl_sync(0xffffffffu, acc.y, m)));
        }
        float2 m0 = unpack2(o0), m1 = unpack2(o1);
        epilogue(n, lane, make_float2(m0.x + m1.x, m0.y + m1.y),
                 slot, npairs, wr_next, wdst, p);
    }

#pragma unroll
    for (int j = 0; j < 5; ++j)
        for (int off = 16; off > 0; off >>= 1)
            p[j] += __shfl_down_sync(0xffffffffu, p[j], off);
    __syncthreads();
    if (lane == 0)
        for (int j = 0; j < 5; ++j) red[warp][j] = (double)p[j];
    __syncthreads();
    if (threadIdx.x < npairs) {
        int j = threadIdx.x;
        double s = 0.0;
        for (int ww = 0; ww < TPB / 32; ww++) s += red[ww][j];
        atomicAdd(&target[j], s);
    }
}

// ---------------- combine(k): Gram merge + 5x5 solve + u_new (+ fused decode at k=4) ----------------
__device__ void combine_phase(int k, float* sa, const float* __restrict__ decW,
                              float* __restrict__ out) {
    if (threadIdx.x == 0) {
        double M[5][5];
        const double* base = g_GGbuf[k & 1];
        int c = 0;
        for (int i = 0; i < 5; i++)
            for (int j = 0; j <= i; j++) { M[i][j] = base[c]; M[j][i] = base[c]; c++; }
        if (k > 0) {
            int idx = k - 1;
            const double* row = g_GGrow[(k - 1) & 1];
            for (int j = 0; j < 5; j++) { M[idx][j] = row[j]; M[j][idx] = row[j]; }
        }
        if (blockIdx.x == 0 && k < AAM - 1) {
            c = 0;
            for (int i = 0; i < 5; i++)
                for (int j = 0; j <= i; j++) g_GGbuf[(k + 1) & 1][c++] = M[i][j];
            for (int j = 0; j < 5; j++) g_GGrow[k & 1][j] = 0.0;
        }
        float A[5][6];
        for (int i = 0; i < 5; i++) {
            for (int j = 0; j < 5; j++) A[i][j] = (float)M[i][j];
            A[i][i] += 1e-4f;
            A[i][5] = 1.f;
        }
        for (int kk = 0; kk < 5; kk++) {
            int piv = kk; float mx = fabsf(A[kk][kk]);
            for (int r = kk + 1; r < 5; r++)
                if (fabsf(A[r][kk]) > mx) { mx = fabsf(A[r][kk]); piv = r; }
            if (piv != kk)
                for (int j = 0; j < 6; j++) { float t = A[kk][j]; A[kk][j] = A[piv][j]; A[piv][j] = t; }
            float inv = 1.f / A[kk][kk];
            for (int r = kk + 1; r < 5; r++) {
                float f = A[r][kk] * inv;
                for (int j = kk; j < 6; j++) A[r][j] -= f * A[kk][j];
            }
        }
        float a[5];
        for (int kk = 4; kk >= 0; kk--) {
            float s = A[kk][5];
            for (int j = kk + 1; j < 5; j++) s -= A[kk][j] * a[j];
            a[kk] = s / A[kk][kk];
        }
        float sum = a[0] + a[1] + a[2] + a[3] + a[4];
        for (int j = 0; j < 5; j++) sa[j] = a[j] / sum;
    }
    __syncthreads();
    float a0 = sa[0], a1 = sa[1], a2 = sa[2], a3 = sa[3], a4 = sa[4];

    int warp = threadIdx.x >> 5, lane = threadIdx.x & 31;
    int g = blockIdx.x * (TPB / 32) + warp;
    const float2* F0 = (const float2*)g_F[0];
    const float2* F1 = (const float2*)g_F[1];
    const float2* F2 = (const float2*)g_F[2];
    const float2* F3 = (const float2*)g_F[3];
    const float2* F4 = (const float2*)g_F[4];
    for (int node = g; node < N_NODES; node += NWARPS) {
        int idx = node * 32 + lane;
        float2 f0 = F0[idx], f1 = F1[idx], f2 = F2[idx], f3 = F3[idx], f4 = F4[idx];
        float2 un;
        un.x = a0 * f0.x + a1 * f1.x + a2 * f2.x + a3 * f3.x + a4 * f4.x;
        un.y = a0 * f0.y + a1 * f1.y + a2 * f2.y + a3 * f3.y + a4 * f4.y;
        if (k < AAM - 1) {
            ((float2*)g_u)[idx] = un;
            float2 bb = ((const float2*)g_b)[idx];
            ((float2*)g_wbuf[0])[idx] =
                make_float2(2.f * fmaxf(un.x, 0.f) - un.x + bb.x,
                            2.f * fmaxf(un.y, 0.f) - un.y + bb.y);
        } else {
            float rx = fmaxf(un.x, 0.f), ry = fmaxf(un.y, 0.f);
            int o = lane & 15, half = lane >> 4;
            float acc = 0.f;
#pragma unroll
            for (int i = 0; i < 16; i++) {
                int m = half * 16 + i;
                float sx = __shfl_sync(0xffffffffu, rx, m);
                float sy = __shfl_sync(0xffffffffu, ry, m);
                acc = fmaf(sx, decW[(2 * m) * 16 + o], acc);
                acc = fmaf(sy, decW[(2 * m + 1) * 16 + o], acc);
            }
            acc += __shfl_down_sync(0xffffffffu, acc, 16);
            if (half == 0) out[node * 16 + o] = acc;
        }
    }
}

// ---------------- the single persistent kernel ----------------
__global__ void __launch_bounds__(TPB, 2) k_mega(
    const float* __restrict__ x, const int* __restrict__ ei,
    const float* __restrict__ ew, const float* __restrict__ encW,
    const float* __restrict__ encb, const float* __restrict__ cayB,
    const float* __restrict__ decW, float* __restrict__ out)
{
    __shared__ SmemU su;
    __shared__ double red[TPB / 32][5];
    __shared__ float sa[5];

    const int* src = ei;
    const int* dst = ei + N_EDGES;
    int gtid = blockIdx.x * TPB + threadIdx.x;

    // A: zero counters + Gram buf
    for (int i = gtid; i < N_NODES; i += NTHREADS) g_cur[i] = 0;
    if (gtid < 15) g_GGbuf[0][gtid] = 0.0;
    gbar();

    // B: degree histogram || encoder + u0/w0
    for (int e = gtid; e < N_EDGES; e += NTHREADS) atomicAdd(&g_cur[dst[e]], 1);
    encode_phase(x, encW, encb);
    gbar();

    // C: prefix scan (block 0) || Cayley theta (block 1)
    if (blockIdx.x == 0) {
        int t = threadIdx.x;
        const int CH = (N_NODES + TPB - 1) / TPB;   // 20
        int beg = t * CH, end = beg + CH; if (end > N_NODES) end = N_NODES;
        int s = 0;
        for (int i = beg; i < end; i++) s += g_cur[i];
        su.part[t] = s;
        __syncthreads();
        for (int d = 1; d < TPB; d <<= 1) {
            int v = (t >= d) ? su.part[t - d] : 0;
            __syncthreads();
            su.part[t] += v;
            __syncthreads();
        }
        int off = (t > 0) ? su.part[t - 1] : 0;
        for (int i = beg; i < end; i++) {
            int c = g_cur[i];
            g_rowptr[i] = off;
            g_cur[i]    = off;
            off += c;
        }
        if (t == 0) g_rowptr[N_NODES] = N_EDGES;
    } else if (blockIdx.x == 1) {
        theta_phase(cayB, &su);
    }
    gbar();

    // D: CSR scatter || balanced warp partition (binary search on cost) || stage Theta
    for (int e = gtid; e < N_EDGES; e += NTHREADS) {
        int d = dst[e];
        int p = atomicAdd(&g_cur[d], 1);
        g_edge[p] = make_int2(src[e], __float_as_int(ew[e]));
    }
    if (gtid <= NWARPS) {
        if (gtid == NWARPS) {
            g_wstart[NWARPS] = N_NODES;
        } else {
            long long target = (long long)gtid * COST_TOTAL / NWARPS;
            int lo = 0, hi = N_NODES;
            while (lo < hi) {
                int mid = (lo + hi) >> 1;
                long long c = (long long)g_rowptr[mid] + 16LL * mid;
                if (c < target) lo = mid + 1; else hi = mid;
            }
            g_wstart[gtid] = lo;
        }
    }
    for (int i = threadIdx.x; i < D_HID * 32; i += TPB)
        ((ull*)su.sThU)[i] = ((const ull*)g_ThT)[i];
    gbar();

    // history: 5 PR sweeps (w ping-pong), Gram lower-tri into GGbuf[0]
    for (int i = 0; i < AAM; i++) {
        spmm_phase(i, i + 1, &g_GGbuf[0][i * (i + 1) / 2], (i < AAM - 1) ? 1 : 0,
                   g_wbuf[i & 1], g_wbuf[(i + 1) & 1], &su, red);
        gbar();
    }

    // Anderson: combine -> spmm (last g() dead); final combine fuses decode
    for (int k = 0; k < AAM; k++) {
        combine_phase(k, sa, decW, out);
        if (k < AAM - 1) {
            gbar();
            spmm_phase(k, 5, g_GGrow[k & 1], 0, g_wbuf[0], 0, &su, red);
            gbar();
        }
    }
}

// ---------------- launch: ONE kernel ----------------
extern "C" void kernel_launch(void* const* d_in, const int* in_sizes, int n_in,
                              void* d_out, int out_size) {
    const float* x    = (const float*)d_in[0];
    const int*   ei   = (const int*)  d_in[1];
    const float* ew   = (const float*)d_in[2];
    const float* encW = (const float*)d_in[3];
    const float* encb = (const float*)d_in[4];
    const float* cayB = (const float*)d_in[5];
    const float* decW = (const float*)d_in[6];
    float* out = (float*)d_out;

    k_mega<<<GRID_BLOCKS, TPB>>>(x, ei, ew, encW, encb, cayB, decW, out);
}